// round 2
// baseline (speedup 1.0000x reference)
#include <cuda_runtime.h>
#include <math.h>

#define N_SRC 50000
#define N_DST 50000
#define E_NUM 800000
#define D_IN  64
#define HID   256
#define HEADS 4
#define FPH   64
#define N_ACT 16
#define G3    (3*HID)   // 768

// ---------------- scratch (device globals; no runtime allocation) ----------------
__device__ float g_fs[(size_t)N_SRC * HID];      // src projected feats
__device__ float g_fd[(size_t)N_DST * HID];      // dst projected feats
__device__ float g_res[(size_t)N_DST * HID];     // residual proj
__device__ float g_x[(size_t)N_DST * HID];       // aggregated messages -> GAT output
__device__ float g_score[(size_t)E_NUM * HEADS]; // per-edge per-head scores
__device__ float g_smax[(size_t)N_DST * HEADS];  // segment max
__device__ float g_den[(size_t)N_DST * HEADS];   // segment sum of exp
__device__ float g_gi[(size_t)N_DST * G3];       // GRU input gates
__device__ float g_gh[(size_t)N_DST * G3];       // GRU hidden gates

// ---------------- helpers ----------------
__device__ __forceinline__ void atomicMaxFloat(float* addr, float val) {
    if (val >= 0.0f) atomicMax((int*)addr, __float_as_int(val));
    else             atomicMin((unsigned int*)addr, __float_as_uint(val));
}

// ---------------- init ----------------
__global__ void init_kernel() {
    int idx = blockIdx.x * blockDim.x + threadIdx.x;
    if (idx < N_DST * HID) g_x[idx] = 0.0f;
    if (idx < N_DST * HEADS) {
        g_smax[idx] = -INFINITY;
        g_den[idx]  = 0.0f;
    }
}

// ---------------- tiled SGEMM: C[M,N] = A[M,K] @ op(B) + bias ----------------
// BT=false: B is [K,N] row-major.   BT=true: B is [N,K] row-major (i.e. A @ B^T).
// Tiles: 64x64x16, 16x16 threads, 4x4 per thread. N,K assumed multiples of 64/16; M guarded.
template <bool BT>
__global__ void sgemm64(const float* __restrict__ A, const float* __restrict__ B,
                        const float* __restrict__ bias, float* __restrict__ C,
                        int M, int N, int K) {
    __shared__ float As[16][64];
    __shared__ float Bs[16][64];

    const int tx = threadIdx.x, ty = threadIdx.y;
    const int tid = ty * 16 + tx;
    const int m0 = blockIdx.y * 64;
    const int n0 = blockIdx.x * 64;

    const int arow = tid >> 2;        // 0..63
    const int ac4  = tid & 3;         // 0..3  (float4 within K-tile)
    // B loader indices
    const int brow_t = tid >> 2;      // BT: n index 0..63
    const int bc4_t  = tid & 3;       // BT: k float4
    const int brow_n = tid >> 4;      // !BT: k index 0..15
    const int bc4_n  = tid & 15;      // !BT: n float4

    float acc[4][4] = {};

    for (int k0 = 0; k0 < K; k0 += 16) {
        // load A tile (transposed into smem)
        float4 av = make_float4(0.f, 0.f, 0.f, 0.f);
        int gr = m0 + arow;
        if (gr < M) av = *(const float4*)(A + (size_t)gr * K + k0 + ac4 * 4);
        As[ac4 * 4 + 0][arow] = av.x;
        As[ac4 * 4 + 1][arow] = av.y;
        As[ac4 * 4 + 2][arow] = av.z;
        As[ac4 * 4 + 3][arow] = av.w;

        // load B tile
        if (BT) {
            float4 bv = *(const float4*)(B + (size_t)(n0 + brow_t) * K + k0 + bc4_t * 4);
            Bs[bc4_t * 4 + 0][brow_t] = bv.x;
            Bs[bc4_t * 4 + 1][brow_t] = bv.y;
            Bs[bc4_t * 4 + 2][brow_t] = bv.z;
            Bs[bc4_t * 4 + 3][brow_t] = bv.w;
        } else {
            float4 bv = *(const float4*)(B + (size_t)(k0 + brow_n) * N + n0 + bc4_n * 4);
            Bs[brow_n][bc4_n * 4 + 0] = bv.x;
            Bs[brow_n][bc4_n * 4 + 1] = bv.y;
            Bs[brow_n][bc4_n * 4 + 2] = bv.z;
            Bs[brow_n][bc4_n * 4 + 3] = bv.w;
        }
        __syncthreads();

        #pragma unroll
        for (int kk = 0; kk < 16; kk++) {
            float ar[4], br[4];
            #pragma unroll
            for (int i = 0; i < 4; i++) ar[i] = As[kk][ty * 4 + i];
            #pragma unroll
            for (int j = 0; j < 4; j++) br[j] = Bs[kk][tx * 4 + j];
            #pragma unroll
            for (int i = 0; i < 4; i++)
                #pragma unroll
                for (int j = 0; j < 4; j++)
                    acc[i][j] = fmaf(ar[i], br[j], acc[i][j]);
        }
        __syncthreads();
    }

    #pragma unroll
    for (int i = 0; i < 4; i++) {
        int gr = m0 + ty * 4 + i;
        if (gr >= M) continue;
        #pragma unroll
        for (int j = 0; j < 4; j++) {
            int gc = n0 + tx * 4 + j;
            C[(size_t)gr * N + gc] = acc[i][j] + bias[gc];
        }
    }
}

// ---------------- edge pass 1: scores + segment max ----------------
// one warp per edge; lane handles 8 contiguous features; lanes 8h..8h+7 are head h.
__global__ void edge_score_kernel(const int* __restrict__ esrc, const int* __restrict__ edst,
                                  const float* __restrict__ attn) {
    __shared__ float s_attn[HID];
    int tid = threadIdx.x;
    s_attn[tid] = attn[tid];
    __syncthreads();

    int warp = tid >> 5, lane = tid & 31;
    int e = blockIdx.x * 8 + warp;
    if (e >= E_NUM) return;
    int s = esrc[e], d = edst[e];

    const float4* pfs = (const float4*)(g_fs + (size_t)s * HID + lane * 8);
    const float4* pfd = (const float4*)(g_fd + (size_t)d * HID + lane * 8);
    float4 a0 = pfs[0], a1 = pfs[1];
    float4 b0 = pfd[0], b1 = pfd[1];
    const float* at = s_attn + lane * 8;

    float sum = 0.0f, v;
    v = a0.x + b0.x; v = fmaxf(v, 0.2f * v); sum = fmaf(v, at[0], sum);
    v = a0.y + b0.y; v = fmaxf(v, 0.2f * v); sum = fmaf(v, at[1], sum);
    v = a0.z + b0.z; v = fmaxf(v, 0.2f * v); sum = fmaf(v, at[2], sum);
    v = a0.w + b0.w; v = fmaxf(v, 0.2f * v); sum = fmaf(v, at[3], sum);
    v = a1.x + b1.x; v = fmaxf(v, 0.2f * v); sum = fmaf(v, at[4], sum);
    v = a1.y + b1.y; v = fmaxf(v, 0.2f * v); sum = fmaf(v, at[5], sum);
    v = a1.z + b1.z; v = fmaxf(v, 0.2f * v); sum = fmaf(v, at[6], sum);
    v = a1.w + b1.w; v = fmaxf(v, 0.2f * v); sum = fmaf(v, at[7], sum);

    sum += __shfl_down_sync(0xffffffffu, sum, 4, 8);
    sum += __shfl_down_sync(0xffffffffu, sum, 2, 8);
    sum += __shfl_down_sync(0xffffffffu, sum, 1, 8);

    if ((lane & 7) == 0) {
        int h = lane >> 3;
        g_score[(size_t)e * HEADS + h] = sum;
        atomicMaxFloat(&g_smax[(size_t)d * HEADS + h], sum);
    }
}

// ---------------- edge pass 2: exp + denom + unnormalized message scatter ----------------
__global__ void edge_msg_kernel(const int* __restrict__ esrc, const int* __restrict__ edst) {
    int tid = threadIdx.x;
    int warp = tid >> 5, lane = tid & 31;
    int e = blockIdx.x * 8 + warp;
    if (e >= E_NUM) return;
    int s = esrc[e], d = edst[e];

    int h = lane >> 3;
    float sc = g_score[(size_t)e * HEADS + h];
    float mx = g_smax[(size_t)d * HEADS + h];
    float ex = __expf(sc - mx);
    if ((lane & 7) == 0) atomicAdd(&g_den[(size_t)d * HEADS + h], ex);

    const float4* pfs = (const float4*)(g_fs + (size_t)s * HID + lane * 8);
    float4 a0 = pfs[0], a1 = pfs[1];
    float* px = g_x + (size_t)d * HID + lane * 8;
    atomicAdd(px + 0, ex * a0.x);
    atomicAdd(px + 1, ex * a0.y);
    atomicAdd(px + 2, ex * a0.z);
    atomicAdd(px + 3, ex * a0.w);
    atomicAdd(px + 4, ex * a1.x);
    atomicAdd(px + 5, ex * a1.y);
    atomicAdd(px + 6, ex * a1.z);
    atomicAdd(px + 7, ex * a1.w);
}

// ---------------- node epilogue: normalize, residual, relu ----------------
__global__ void node_post_kernel() {
    int idx = blockIdx.x * blockDim.x + threadIdx.x;
    if (idx >= N_DST * HID) return;
    int i = idx >> 8;
    int j = idx & 255;
    int h = j >> 6;
    float dnm = g_den[(size_t)i * HEADS + h];
    float v = (dnm > 0.0f) ? (g_x[idx] / dnm) : 0.0f;
    v += g_res[idx];
    g_x[idx] = fmaxf(v, 0.0f);
}

// ---------------- GRU elementwise ----------------
__global__ void gru_kernel(const float* __restrict__ h0, float* __restrict__ hout) {
    int idx = blockIdx.x * blockDim.x + threadIdx.x;
    if (idx >= N_DST * HID) return;
    int i = idx >> 8;
    int j = idx & 255;
    size_t b = (size_t)i * G3;
    float r = g_gi[b + j]           + g_gh[b + j];
    float z = g_gi[b + HID + j]     + g_gh[b + HID + j];
    r = 1.0f / (1.0f + expf(-r));
    z = 1.0f / (1.0f + expf(-z));
    float n = tanhf(g_gi[b + 2 * HID + j] + r * g_gh[b + 2 * HID + j]);
    hout[idx] = (1.0f - z) * n + z * h0[idx];
}

// ---------------- logits head: 16 rows x 16 cols per 256-thread block ----------------
__global__ void logits_kernel(const float* __restrict__ h, const float* __restrict__ Wout,
                              const float* __restrict__ bout, float* __restrict__ out) {
    __shared__ float sW[HID * N_ACT];
    int tid = threadIdx.x;
    for (int t = tid; t < HID * N_ACT; t += 256) sW[t] = Wout[t];
    __syncthreads();

    int row = blockIdx.x * 16 + (tid >> 4);
    int col = tid & 15;
    if (row >= N_DST) return;
    const float* hr = h + (size_t)row * HID;
    float acc = bout[col];
    #pragma unroll 8
    for (int k = 0; k < HID; k++) acc = fmaf(hr[k], sW[k * N_ACT + col], acc);
    out[(size_t)row * N_ACT + col] = acc;
}

// ---------------- launch ----------------
extern "C" void kernel_launch(void* const* d_in, const int* in_sizes, int n_in,
                              void* d_out, int out_size) {
    const float* feat_gt    = (const float*)d_in[0];
    const float* feat_agent = (const float*)d_in[1];
    const float* h0         = (const float*)d_in[2];
    const int*   edge_src   = (const int*)d_in[3];
    const int*   edge_dst   = (const int*)d_in[4];
    const float* W_src      = (const float*)d_in[5];
    const float* b_src      = (const float*)d_in[6];
    const float* W_dst      = (const float*)d_in[7];
    const float* b_dst      = (const float*)d_in[8];
    const float* attn       = (const float*)d_in[9];
    const float* W_res      = (const float*)d_in[10];
    const float* b_res      = (const float*)d_in[11];
    const float* W_ih       = (const float*)d_in[12];
    const float* W_hh       = (const float*)d_in[13];
    const float* b_ih       = (const float*)d_in[14];
    const float* b_hh       = (const float*)d_in[15];
    const float* W_out      = (const float*)d_in[16];
    const float* b_out      = (const float*)d_in[17];

    float* out_logits = (float*)d_out;
    float* out_h      = (float*)d_out + (size_t)N_DST * N_ACT;

    float *p_fs, *p_fd, *p_res, *p_x, *p_gi, *p_gh;
    cudaGetSymbolAddress((void**)&p_fs,  g_fs);
    cudaGetSymbolAddress((void**)&p_fd,  g_fd);
    cudaGetSymbolAddress((void**)&p_res, g_res);
    cudaGetSymbolAddress((void**)&p_x,   g_x);
    cudaGetSymbolAddress((void**)&p_gi,  g_gi);
    cudaGetSymbolAddress((void**)&p_gh,  g_gh);

    dim3 blk(16, 16);
    const int NELEM = N_DST * HID;

    init_kernel<<<(NELEM + 255) / 256, 256>>>();

    // feature projections
    sgemm64<false><<<dim3(HID / 64, (N_SRC + 63) / 64), blk>>>(feat_gt,    W_src, b_src, p_fs,  N_SRC, HID, D_IN);
    sgemm64<false><<<dim3(HID / 64, (N_DST + 63) / 64), blk>>>(feat_agent, W_dst, b_dst, p_fd,  N_DST, HID, D_IN);
    sgemm64<false><<<dim3(HID / 64, (N_DST + 63) / 64), blk>>>(feat_agent, W_res, b_res, p_res, N_DST, HID, D_IN);

    // GATv2 edge passes
    edge_score_kernel<<<(E_NUM + 7) / 8, 256>>>(edge_src, edge_dst, attn);
    edge_msg_kernel<<<(E_NUM + 7) / 8, 256>>>(edge_src, edge_dst);
    node_post_kernel<<<(NELEM + 255) / 256, 256>>>();

    // GRU gates (A @ W^T)
    sgemm64<true><<<dim3(G3 / 64, (N_DST + 63) / 64), blk>>>(p_x, W_ih, b_ih, p_gi, N_DST, G3, HID);
    sgemm64<true><<<dim3(G3 / 64, (N_DST + 63) / 64), blk>>>(h0,  W_hh, b_hh, p_gh, N_DST, G3, HID);

    gru_kernel<<<(NELEM + 255) / 256, 256>>>(h0, out_h);

    logits_kernel<<<(N_DST + 15) / 16, 256>>>(out_h, W_out, b_out, out_logits);
}

// round 3
// speedup vs baseline: 1.4752x; 1.4752x over previous
#include <cuda_runtime.h>
#include <math.h>

#define N_SRC 50000
#define N_DST 50000
#define E_NUM 800000
#define D_IN  64
#define HID   256
#define HEADS 4
#define FPH   64
#define N_ACT 16
#define G3    (3*HID)   // 768

// ---------------- scratch (device globals; no runtime allocation) ----------------
__device__ float g_fs[(size_t)N_SRC * HID];      // src projected feats
__device__ float g_fd[(size_t)N_DST * HID];      // dst projected feats
__device__ float g_res[(size_t)N_DST * HID];     // residual proj
__device__ float g_x[(size_t)N_DST * HID];       // aggregated messages -> GAT output
__device__ float g_score[(size_t)E_NUM * HEADS]; // per-edge per-head scores
__device__ float g_smax[(size_t)N_DST * HEADS];  // segment max
__device__ float g_den[(size_t)N_DST * HEADS];   // segment sum of exp
__device__ float g_gi[(size_t)N_DST * G3];       // GRU input gates
__device__ float g_gh[(size_t)N_DST * G3];       // GRU hidden gates

// ---------------- helpers ----------------
__device__ __forceinline__ void atomicMaxFloat(float* addr, float val) {
    if (val >= 0.0f) atomicMax((int*)addr, __float_as_int(val));
    else             atomicMin((unsigned int*)addr, __float_as_uint(val));
}

__device__ __forceinline__ void redAddV4(float* p, float a, float b, float c, float d) {
    asm volatile("red.global.add.v4.f32 [%0], {%1,%2,%3,%4};"
                 :: "l"(p), "f"(a), "f"(b), "f"(c), "f"(d) : "memory");
}

// ---------------- init ----------------
__global__ void init_kernel() {
    int idx = blockIdx.x * blockDim.x + threadIdx.x;
    if (idx < N_DST * HID) g_x[idx] = 0.0f;
    if (idx < N_DST * HEADS) {
        g_smax[idx] = -INFINITY;
        g_den[idx]  = 0.0f;
    }
}

// ---------------- SGEMM: C[M,N] = A[M,K] @ op(B) + bias ----------------
// 128x128x16 tiles, 256 threads, 8x8 per thread, double-buffered smem.
// BT=false: B is [K,N] row-major. BT=true: B is [N,K] row-major (A @ B^T).
// Requires: N % 128 == 0, K % 16 == 0. M guarded.
template <bool BT>
__global__ __launch_bounds__(256)
void sgemm128(const float* __restrict__ A, const float* __restrict__ B,
              const float* __restrict__ bias, float* __restrict__ C,
              int M, int N, int K) {
    __shared__ float As[2][16][128];
    __shared__ float Bs[2][16][128];

    const int tid = threadIdx.x;
    const int tx  = tid & 15;          // 0..15 -> n sub-tile
    const int ty  = tid >> 4;          // 0..15 -> m sub-tile
    const int m0  = blockIdx.y * 128;
    const int n0  = blockIdx.x * 128;

    // A / BT-B loader indices: row = tid>>2 (+64), k-float4 = tid&3
    const int lrow = tid >> 2;         // 0..63
    const int lk4  = (tid & 3) * 4;    // 0,4,8,12
    // !BT B loader: k row = tid>>4, n-float4 = tid&15 (+16)
    const int bk  = tid >> 4;          // 0..15
    const int bn4 = (tid & 15) * 4;    // 0..60

    const int nk = K / 16;
    float4 ra0, ra1, rb0, rb1;

    auto fetch = [&](int k0) {
        int r0 = m0 + lrow, r1 = m0 + lrow + 64;
        ra0 = (r0 < M) ? *(const float4*)(A + (size_t)r0 * K + k0 + lk4)
                       : make_float4(0.f, 0.f, 0.f, 0.f);
        ra1 = (r1 < M) ? *(const float4*)(A + (size_t)r1 * K + k0 + lk4)
                       : make_float4(0.f, 0.f, 0.f, 0.f);
        if (BT) {
            rb0 = *(const float4*)(B + (size_t)(n0 + lrow)      * K + k0 + lk4);
            rb1 = *(const float4*)(B + (size_t)(n0 + lrow + 64) * K + k0 + lk4);
        } else {
            rb0 = *(const float4*)(B + (size_t)(k0 + bk) * N + n0 + bn4);
            rb1 = *(const float4*)(B + (size_t)(k0 + bk) * N + n0 + bn4 + 64);
        }
    };
    auto store = [&](int buf) {
        As[buf][lk4 + 0][lrow] = ra0.x; As[buf][lk4 + 1][lrow] = ra0.y;
        As[buf][lk4 + 2][lrow] = ra0.z; As[buf][lk4 + 3][lrow] = ra0.w;
        As[buf][lk4 + 0][lrow + 64] = ra1.x; As[buf][lk4 + 1][lrow + 64] = ra1.y;
        As[buf][lk4 + 2][lrow + 64] = ra1.z; As[buf][lk4 + 3][lrow + 64] = ra1.w;
        if (BT) {
            Bs[buf][lk4 + 0][lrow] = rb0.x; Bs[buf][lk4 + 1][lrow] = rb0.y;
            Bs[buf][lk4 + 2][lrow] = rb0.z; Bs[buf][lk4 + 3][lrow] = rb0.w;
            Bs[buf][lk4 + 0][lrow + 64] = rb1.x; Bs[buf][lk4 + 1][lrow + 64] = rb1.y;
            Bs[buf][lk4 + 2][lrow + 64] = rb1.z; Bs[buf][lk4 + 3][lrow + 64] = rb1.w;
        } else {
            *(float4*)&Bs[buf][bk][bn4]      = rb0;
            *(float4*)&Bs[buf][bk][bn4 + 64] = rb1;
        }
    };

    float acc[8][8] = {};

    fetch(0); store(0);
    __syncthreads();
    int buf = 0;

    for (int t = 0; t < nk; t++) {
        if (t + 1 < nk) fetch((t + 1) * 16);

        #pragma unroll
        for (int kk = 0; kk < 16; kk++) {
            float4 al = *(const float4*)&As[buf][kk][ty * 8];
            float4 ah = *(const float4*)&As[buf][kk][ty * 8 + 4];
            float4 bl = *(const float4*)&Bs[buf][kk][tx * 8];
            float4 bh = *(const float4*)&Bs[buf][kk][tx * 8 + 4];
            float ar[8] = {al.x, al.y, al.z, al.w, ah.x, ah.y, ah.z, ah.w};
            float br[8] = {bl.x, bl.y, bl.z, bl.w, bh.x, bh.y, bh.z, bh.w};
            #pragma unroll
            for (int i = 0; i < 8; i++)
                #pragma unroll
                for (int j = 0; j < 8; j++)
                    acc[i][j] = fmaf(ar[i], br[j], acc[i][j]);
        }

        if (t + 1 < nk) {
            store(buf ^ 1);
            __syncthreads();
            buf ^= 1;
        }
    }

    // epilogue: bias + store (float4)
    float4 bi0 = *(const float4*)(bias + n0 + tx * 8);
    float4 bi1 = *(const float4*)(bias + n0 + tx * 8 + 4);
    #pragma unroll
    for (int i = 0; i < 8; i++) {
        int gr = m0 + ty * 8 + i;
        if (gr >= M) continue;
        float4 v0 = make_float4(acc[i][0] + bi0.x, acc[i][1] + bi0.y,
                                acc[i][2] + bi0.z, acc[i][3] + bi0.w);
        float4 v1 = make_float4(acc[i][4] + bi1.x, acc[i][5] + bi1.y,
                                acc[i][6] + bi1.z, acc[i][7] + bi1.w);
        *(float4*)(C + (size_t)gr * N + n0 + tx * 8)     = v0;
        *(float4*)(C + (size_t)gr * N + n0 + tx * 8 + 4) = v1;
    }
}

// ---------------- edge pass 1: scores + segment max ----------------
__global__ void edge_score_kernel(const int* __restrict__ esrc, const int* __restrict__ edst,
                                  const float* __restrict__ attn) {
    __shared__ float s_attn[HID];
    int tid = threadIdx.x;
    s_attn[tid] = attn[tid];
    __syncthreads();

    int warp = tid >> 5, lane = tid & 31;
    int e = blockIdx.x * 8 + warp;
    if (e >= E_NUM) return;
    int s = esrc[e], d = edst[e];

    const float4* pfs = (const float4*)(g_fs + (size_t)s * HID + lane * 8);
    const float4* pfd = (const float4*)(g_fd + (size_t)d * HID + lane * 8);
    float4 a0 = pfs[0], a1 = pfs[1];
    float4 b0 = pfd[0], b1 = pfd[1];
    const float* at = s_attn + lane * 8;

    float sum = 0.0f, v;
    v = a0.x + b0.x; v = fmaxf(v, 0.2f * v); sum = fmaf(v, at[0], sum);
    v = a0.y + b0.y; v = fmaxf(v, 0.2f * v); sum = fmaf(v, at[1], sum);
    v = a0.z + b0.z; v = fmaxf(v, 0.2f * v); sum = fmaf(v, at[2], sum);
    v = a0.w + b0.w; v = fmaxf(v, 0.2f * v); sum = fmaf(v, at[3], sum);
    v = a1.x + b1.x; v = fmaxf(v, 0.2f * v); sum = fmaf(v, at[4], sum);
    v = a1.y + b1.y; v = fmaxf(v, 0.2f * v); sum = fmaf(v, at[5], sum);
    v = a1.z + b1.z; v = fmaxf(v, 0.2f * v); sum = fmaf(v, at[6], sum);
    v = a1.w + b1.w; v = fmaxf(v, 0.2f * v); sum = fmaf(v, at[7], sum);

    sum += __shfl_down_sync(0xffffffffu, sum, 4, 8);
    sum += __shfl_down_sync(0xffffffffu, sum, 2, 8);
    sum += __shfl_down_sync(0xffffffffu, sum, 1, 8);

    if ((lane & 7) == 0) {
        int h = lane >> 3;
        g_score[(size_t)e * HEADS + h] = sum;
        atomicMaxFloat(&g_smax[(size_t)d * HEADS + h], sum);
    }
}

// ---------------- edge pass 2: exp + denom + message scatter (vector RED) ----------------
__global__ void edge_msg_kernel(const int* __restrict__ esrc, const int* __restrict__ edst) {
    int tid = threadIdx.x;
    int warp = tid >> 5, lane = tid & 31;
    int e = blockIdx.x * 8 + warp;
    if (e >= E_NUM) return;
    int s = esrc[e], d = edst[e];

    int h = lane >> 3;
    float sc = g_score[(size_t)e * HEADS + h];
    float mx = g_smax[(size_t)d * HEADS + h];
    float ex = __expf(sc - mx);
    if ((lane & 7) == 0) atomicAdd(&g_den[(size_t)d * HEADS + h], ex);

    const float4* pfs = (const float4*)(g_fs + (size_t)s * HID + lane * 8);
    float4 a0 = pfs[0], a1 = pfs[1];
    float* px = g_x + (size_t)d * HID + lane * 8;
    redAddV4(px,     ex * a0.x, ex * a0.y, ex * a0.z, ex * a0.w);
    redAddV4(px + 4, ex * a1.x, ex * a1.y, ex * a1.z, ex * a1.w);
}

// ---------------- node epilogue: normalize, residual, relu ----------------
__global__ void node_post_kernel() {
    int idx = blockIdx.x * blockDim.x + threadIdx.x;
    if (idx >= N_DST * HID) return;
    int i = idx >> 8;
    int j = idx & 255;
    int h = j >> 6;
    float dnm = g_den[(size_t)i * HEADS + h];
    float v = (dnm > 0.0f) ? (g_x[idx] / dnm) : 0.0f;
    v += g_res[idx];
    g_x[idx] = fmaxf(v, 0.0f);
}

// ---------------- GRU elementwise ----------------
__global__ void gru_kernel(const float* __restrict__ h0, float* __restrict__ hout) {
    int idx = blockIdx.x * blockDim.x + threadIdx.x;
    if (idx >= N_DST * HID) return;
    int i = idx >> 8;
    int j = idx & 255;
    size_t b = (size_t)i * G3;
    float r = g_gi[b + j]           + g_gh[b + j];
    float z = g_gi[b + HID + j]     + g_gh[b + HID + j];
    r = 1.0f / (1.0f + expf(-r));
    z = 1.0f / (1.0f + expf(-z));
    float n = tanhf(g_gi[b + 2 * HID + j] + r * g_gh[b + 2 * HID + j]);
    hout[idx] = (1.0f - z) * n + z * h0[idx];
}

// ---------------- logits head ----------------
__global__ void logits_kernel(const float* __restrict__ h, const float* __restrict__ Wout,
                              const float* __restrict__ bout, float* __restrict__ out) {
    __shared__ float sW[HID * N_ACT];
    int tid = threadIdx.x;
    for (int t = tid; t < HID * N_ACT; t += 256) sW[t] = Wout[t];
    __syncthreads();

    int row = blockIdx.x * 16 + (tid >> 4);
    int col = tid & 15;
    if (row >= N_DST) return;
    const float* hr = h + (size_t)row * HID;
    float acc = bout[col];
    #pragma unroll 8
    for (int k = 0; k < HID; k++) acc = fmaf(hr[k], sW[k * N_ACT + col], acc);
    out[(size_t)row * N_ACT + col] = acc;
}

// ---------------- launch ----------------
extern "C" void kernel_launch(void* const* d_in, const int* in_sizes, int n_in,
                              void* d_out, int out_size) {
    const float* feat_gt    = (const float*)d_in[0];
    const float* feat_agent = (const float*)d_in[1];
    const float* h0         = (const float*)d_in[2];
    const int*   edge_src   = (const int*)d_in[3];
    const int*   edge_dst   = (const int*)d_in[4];
    const float* W_src      = (const float*)d_in[5];
    const float* b_src      = (const float*)d_in[6];
    const float* W_dst      = (const float*)d_in[7];
    const float* b_dst      = (const float*)d_in[8];
    const float* attn       = (const float*)d_in[9];
    const float* W_res      = (const float*)d_in[10];
    const float* b_res      = (const float*)d_in[11];
    const float* W_ih       = (const float*)d_in[12];
    const float* W_hh       = (const float*)d_in[13];
    const float* b_ih       = (const float*)d_in[14];
    const float* b_hh       = (const float*)d_in[15];
    const float* W_out      = (const float*)d_in[16];
    const float* b_out      = (const float*)d_in[17];

    float* out_logits = (float*)d_out;
    float* out_h      = (float*)d_out + (size_t)N_DST * N_ACT;

    float *p_fs, *p_fd, *p_res, *p_x, *p_gi, *p_gh;
    cudaGetSymbolAddress((void**)&p_fs,  g_fs);
    cudaGetSymbolAddress((void**)&p_fd,  g_fd);
    cudaGetSymbolAddress((void**)&p_res, g_res);
    cudaGetSymbolAddress((void**)&p_x,   g_x);
    cudaGetSymbolAddress((void**)&p_gi,  g_gi);
    cudaGetSymbolAddress((void**)&p_gh,  g_gh);

    const int NELEM = N_DST * HID;
    const int MB = (N_DST + 127) / 128;   // 391 row-blocks

    init_kernel<<<(NELEM + 255) / 256, 256>>>();

    // feature projections (K=64)
    sgemm128<false><<<dim3(HID / 128, MB), 256>>>(feat_gt,    W_src, b_src, p_fs,  N_SRC, HID, D_IN);
    sgemm128<false><<<dim3(HID / 128, MB), 256>>>(feat_agent, W_dst, b_dst, p_fd,  N_DST, HID, D_IN);
    sgemm128<false><<<dim3(HID / 128, MB), 256>>>(feat_agent, W_res, b_res, p_res, N_DST, HID, D_IN);

    // GATv2 edge passes
    edge_score_kernel<<<(E_NUM + 7) / 8, 256>>>(edge_src, edge_dst, attn);
    edge_msg_kernel<<<(E_NUM + 7) / 8, 256>>>(edge_src, edge_dst);
    node_post_kernel<<<(NELEM + 255) / 256, 256>>>();

    // GRU gates (A @ W^T, K=256, N=768)
    sgemm128<true><<<dim3(G3 / 128, MB), 256>>>(p_x, W_ih, b_ih, p_gi, N_DST, G3, HID);
    sgemm128<true><<<dim3(G3 / 128, MB), 256>>>(h0,  W_hh, b_hh, p_gh, N_DST, G3, HID);

    gru_kernel<<<(NELEM + 255) / 256, 256>>>(h0, out_h);

    logits_kernel<<<(N_DST + 15) / 16, 256>>>(out_h, W_out, b_out, out_logits);
}

// round 4
// speedup vs baseline: 1.6537x; 1.1209x over previous
#include <cuda_runtime.h>
#include <math.h>
#include <stdint.h>

#define N_SRC 50000
#define N_DST 50000
#define E_NUM 800000
#define D_IN  64
#define HID   256
#define HEADS 4
#define FPH   64
#define N_ACT 16
#define G3    (3*HID)   // 768

// ---------------- scratch (device globals; no runtime allocation) ----------------
__device__ float g_fs[(size_t)N_SRC * HID];
__device__ float g_fd[(size_t)N_DST * HID];
__device__ float g_res[(size_t)N_DST * HID];
__device__ float g_x[(size_t)N_DST * HID];
__device__ float g_score[(size_t)E_NUM * HEADS];
__device__ float g_smax[(size_t)N_DST * HEADS];
__device__ float g_den[(size_t)N_DST * HEADS];
__device__ float g_gi[(size_t)N_DST * G3];
__device__ float g_gh[(size_t)N_DST * G3];

// ---------------- helpers ----------------
__device__ __forceinline__ void atomicMaxFloat(float* addr, float val) {
    if (val >= 0.0f) atomicMax((int*)addr, __float_as_int(val));
    else             atomicMin((unsigned int*)addr, __float_as_uint(val));
}

__device__ __forceinline__ void redAddV4(float* p, float a, float b, float c, float d) {
    asm volatile("red.global.add.v4.f32 [%0], {%1,%2,%3,%4};"
                 :: "l"(p), "f"(a), "f"(b), "f"(c), "f"(d) : "memory");
}

__device__ __forceinline__ void tf32split(float v, float& hi, float& lo) {
    asm("cvt.rna.tf32.f32 %0, %1;" : "=f"(hi) : "f"(v));
    float l = v - hi;
    asm("cvt.rna.tf32.f32 %0, %1;" : "=f"(lo) : "f"(l));
}

#define MMA_TF32(c, a, b)                                                      \
    asm volatile("mma.sync.aligned.m16n8k8.row.col.f32.tf32.tf32.f32 "        \
                 "{%0,%1,%2,%3}, {%4,%5,%6,%7}, {%8,%9}, {%0,%1,%2,%3};"      \
                 : "+f"((c)[0]), "+f"((c)[1]), "+f"((c)[2]), "+f"((c)[3])      \
                 : "r"((a)[0]), "r"((a)[1]), "r"((a)[2]), "r"((a)[3]),        \
                   "r"((b)[0]), "r"((b)[1]))

// ---------------- init ----------------
__global__ void init_kernel() {
    int idx = blockIdx.x * blockDim.x + threadIdx.x;
    if (idx < N_DST * HID) g_x[idx] = 0.0f;
    if (idx < N_DST * HEADS) {
        g_smax[idx] = -INFINITY;
        g_den[idx]  = 0.0f;
    }
}

// ---------------- split-TF32 tensor-core GEMM ----------------
// C[M,N] = A[M,K] @ op(B) + bias, fp32-accurate via 3-term tf32 split.
// BT=false: B is [K,N] row-major. BT=true: B is [N,K] row-major (A @ B^T).
// Block tile 128x128x16, 8 warps, warp tile 32x64 (m16n8k8 grid 2x8).
// Requires N % 128 == 0, K % 16 == 0. M guarded.
#define SMS 136   // smem row stride (==8 mod 32 -> conflict-free frag loads)

template <bool BT>
__global__ __launch_bounds__(256)
void mmagemm(const float* __restrict__ A, const float* __restrict__ B,
             const float* __restrict__ bias, float* __restrict__ C,
             int M, int N, int K) {
    __shared__ float Ash[16][SMS], Asl[16][SMS];
    __shared__ float Bsh[16][SMS], Bsl[16][SMS];

    const int tid  = threadIdx.x;
    const int lane = tid & 31;
    const int warp = tid >> 5;
    const int wm   = warp >> 1;      // 0..3
    const int wn   = warp & 1;       // 0..1
    const int m0   = blockIdx.y * 128;
    const int n0   = blockIdx.x * 128;

    const int lrow = tid >> 2;           // 0..63
    const int lk4  = (tid & 3) * 4;      // 0,4,8,12
    const int bk   = tid >> 4;           // 0..15   (!BT B loader)
    const int bn4  = (tid & 15) * 4;     // 0..60

    const int nk = K / 16;
    float4 ra0, ra1, rb0, rb1;

    auto fetch = [&](int k0) {
        int r0 = m0 + lrow, r1 = m0 + lrow + 64;
        ra0 = (r0 < M) ? *(const float4*)(A + (size_t)r0 * K + k0 + lk4)
                       : make_float4(0.f, 0.f, 0.f, 0.f);
        ra1 = (r1 < M) ? *(const float4*)(A + (size_t)r1 * K + k0 + lk4)
                       : make_float4(0.f, 0.f, 0.f, 0.f);
        if (BT) {
            rb0 = *(const float4*)(B + (size_t)(n0 + lrow)      * K + k0 + lk4);
            rb1 = *(const float4*)(B + (size_t)(n0 + lrow + 64) * K + k0 + lk4);
        } else {
            rb0 = *(const float4*)(B + (size_t)(k0 + bk) * N + n0 + bn4);
            rb1 = *(const float4*)(B + (size_t)(k0 + bk) * N + n0 + bn4 + 64);
        }
    };

    auto storeTile = [&]() {
        const float* pa0 = (const float*)&ra0;
        const float* pa1 = (const float*)&ra1;
        const float* pb0 = (const float*)&rb0;
        const float* pb1 = (const float*)&rb1;
        #pragma unroll
        for (int i = 0; i < 4; i++) {
            float hi, lo;
            tf32split(pa0[i], hi, lo);
            Ash[lk4 + i][lrow] = hi;  Asl[lk4 + i][lrow] = lo;
            tf32split(pa1[i], hi, lo);
            Ash[lk4 + i][lrow + 64] = hi;  Asl[lk4 + i][lrow + 64] = lo;
            if (BT) {
                tf32split(pb0[i], hi, lo);
                Bsh[lk4 + i][lrow] = hi;  Bsl[lk4 + i][lrow] = lo;
                tf32split(pb1[i], hi, lo);
                Bsh[lk4 + i][lrow + 64] = hi;  Bsl[lk4 + i][lrow + 64] = lo;
            } else {
                tf32split(pb0[i], hi, lo);
                Bsh[bk][bn4 + i] = hi;  Bsl[bk][bn4 + i] = lo;
                tf32split(pb1[i], hi, lo);
                Bsh[bk][bn4 + i + 64] = hi;  Bsl[bk][bn4 + i + 64] = lo;
            }
        }
    };

    float c[2][8][4] = {};

    fetch(0); storeTile();
    __syncthreads();

    const int gr = lane >> 2;   // 0..7
    const int gc = lane & 3;    // 0..3

    for (int t = 0; t < nk; t++) {
        if (t + 1 < nk) fetch((t + 1) * 16);

        #pragma unroll
        for (int k8 = 0; k8 < 16; k8 += 8) {
            uint32_t ah[2][4], al[2][4], bh[8][2], bl[8][2];
            #pragma unroll
            for (int mt = 0; mt < 2; mt++) {
                int mb = wm * 32 + mt * 16 + gr;
                ah[mt][0] = __float_as_uint(Ash[k8 + gc][mb]);
                ah[mt][1] = __float_as_uint(Ash[k8 + gc][mb + 8]);
                ah[mt][2] = __float_as_uint(Ash[k8 + 4 + gc][mb]);
                ah[mt][3] = __float_as_uint(Ash[k8 + 4 + gc][mb + 8]);
                al[mt][0] = __float_as_uint(Asl[k8 + gc][mb]);
                al[mt][1] = __float_as_uint(Asl[k8 + gc][mb + 8]);
                al[mt][2] = __float_as_uint(Asl[k8 + 4 + gc][mb]);
                al[mt][3] = __float_as_uint(Asl[k8 + 4 + gc][mb + 8]);
            }
            #pragma unroll
            for (int nt = 0; nt < 8; nt++) {
                int nb = wn * 64 + nt * 8 + gr;
                bh[nt][0] = __float_as_uint(Bsh[k8 + gc][nb]);
                bh[nt][1] = __float_as_uint(Bsh[k8 + 4 + gc][nb]);
                bl[nt][0] = __float_as_uint(Bsl[k8 + gc][nb]);
                bl[nt][1] = __float_as_uint(Bsl[k8 + 4 + gc][nb]);
            }
            #pragma unroll
            for (int mt = 0; mt < 2; mt++)
                #pragma unroll
                for (int nt = 0; nt < 8; nt++) {
                    MMA_TF32(c[mt][nt], ah[mt], bh[nt]);   // hi*hi
                    MMA_TF32(c[mt][nt], ah[mt], bl[nt]);   // hi*lo
                    MMA_TF32(c[mt][nt], al[mt], bh[nt]);   // lo*hi
                }
        }

        if (t + 1 < nk) {
            __syncthreads();
            storeTile();
            __syncthreads();
        }
    }

    // epilogue: bias + store
    #pragma unroll
    for (int mt = 0; mt < 2; mt++) {
        #pragma unroll
        for (int nt = 0; nt < 8; nt++) {
            int row = m0 + wm * 32 + mt * 16 + gr;
            int col = n0 + wn * 64 + nt * 8 + gc * 2;
            float b0 = bias[col], b1 = bias[col + 1];
            if (row < M) {
                float2 v = make_float2(c[mt][nt][0] + b0, c[mt][nt][1] + b1);
                *(float2*)(C + (size_t)row * N + col) = v;
            }
            if (row + 8 < M) {
                float2 v = make_float2(c[mt][nt][2] + b0, c[mt][nt][3] + b1);
                *(float2*)(C + (size_t)(row + 8) * N + col) = v;
            }
        }
    }
}

// ---------------- edge pass 1: scores + segment max ----------------
__global__ void edge_score_kernel(const int* __restrict__ esrc, const int* __restrict__ edst,
                                  const float* __restrict__ attn) {
    __shared__ float s_attn[HID];
    int tid = threadIdx.x;
    s_attn[tid] = attn[tid];
    __syncthreads();

    int warp = tid >> 5, lane = tid & 31;
    int e = blockIdx.x * 8 + warp;
    if (e >= E_NUM) return;
    int s = esrc[e], d = edst[e];

    const float4* pfs = (const float4*)(g_fs + (size_t)s * HID + lane * 8);
    const float4* pfd = (const float4*)(g_fd + (size_t)d * HID + lane * 8);
    float4 a0 = pfs[0], a1 = pfs[1];
    float4 b0 = pfd[0], b1 = pfd[1];
    const float* at = s_attn + lane * 8;

    float sum = 0.0f, v;
    v = a0.x + b0.x; v = fmaxf(v, 0.2f * v); sum = fmaf(v, at[0], sum);
    v = a0.y + b0.y; v = fmaxf(v, 0.2f * v); sum = fmaf(v, at[1], sum);
    v = a0.z + b0.z; v = fmaxf(v, 0.2f * v); sum = fmaf(v, at[2], sum);
    v = a0.w + b0.w; v = fmaxf(v, 0.2f * v); sum = fmaf(v, at[3], sum);
    v = a1.x + b1.x; v = fmaxf(v, 0.2f * v); sum = fmaf(v, at[4], sum);
    v = a1.y + b1.y; v = fmaxf(v, 0.2f * v); sum = fmaf(v, at[5], sum);
    v = a1.z + b1.z; v = fmaxf(v, 0.2f * v); sum = fmaf(v, at[6], sum);
    v = a1.w + b1.w; v = fmaxf(v, 0.2f * v); sum = fmaf(v, at[7], sum);

    sum += __shfl_down_sync(0xffffffffu, sum, 4, 8);
    sum += __shfl_down_sync(0xffffffffu, sum, 2, 8);
    sum += __shfl_down_sync(0xffffffffu, sum, 1, 8);

    if ((lane & 7) == 0) {
        int h = lane >> 3;
        g_score[(size_t)e * HEADS + h] = sum;
        atomicMaxFloat(&g_smax[(size_t)d * HEADS + h], sum);
    }
}

// ---------------- edge pass 2: exp + denom + message scatter (vector RED) ----------------
__global__ void edge_msg_kernel(const int* __restrict__ esrc, const int* __restrict__ edst) {
    int tid = threadIdx.x;
    int warp = tid >> 5, lane = tid & 31;
    int e = blockIdx.x * 8 + warp;
    if (e >= E_NUM) return;
    int s = esrc[e], d = edst[e];

    int h = lane >> 3;
    float sc = g_score[(size_t)e * HEADS + h];
    float mx = g_smax[(size_t)d * HEADS + h];
    float ex = __expf(sc - mx);
    if ((lane & 7) == 0) atomicAdd(&g_den[(size_t)d * HEADS + h], ex);

    const float4* pfs = (const float4*)(g_fs + (size_t)s * HID + lane * 8);
    float4 a0 = pfs[0], a1 = pfs[1];
    float* px = g_x + (size_t)d * HID + lane * 8;
    redAddV4(px,     ex * a0.x, ex * a0.y, ex * a0.z, ex * a0.w);
    redAddV4(px + 4, ex * a1.x, ex * a1.y, ex * a1.z, ex * a1.w);
}

// ---------------- node epilogue: normalize, residual, relu ----------------
__global__ void node_post_kernel() {
    int idx = blockIdx.x * blockDim.x + threadIdx.x;
    if (idx >= N_DST * HID) return;
    int i = idx >> 8;
    int j = idx & 255;
    int h = j >> 6;
    float dnm = g_den[(size_t)i * HEADS + h];
    float v = (dnm > 0.0f) ? (g_x[idx] / dnm) : 0.0f;
    v += g_res[idx];
    g_x[idx] = fmaxf(v, 0.0f);
}

// ---------------- GRU elementwise ----------------
__global__ void gru_kernel(const float* __restrict__ h0, float* __restrict__ hout) {
    int idx = blockIdx.x * blockDim.x + threadIdx.x;
    if (idx >= N_DST * HID) return;
    int i = idx >> 8;
    int j = idx & 255;
    size_t b = (size_t)i * G3;
    float r = g_gi[b + j]           + g_gh[b + j];
    float z = g_gi[b + HID + j]     + g_gh[b + HID + j];
    r = 1.0f / (1.0f + expf(-r));
    z = 1.0f / (1.0f + expf(-z));
    float n = tanhf(g_gi[b + 2 * HID + j] + r * g_gh[b + 2 * HID + j]);
    hout[idx] = (1.0f - z) * n + z * h0[idx];
}

// ---------------- logits head ----------------
__global__ void logits_kernel(const float* __restrict__ h, const float* __restrict__ Wout,
                              const float* __restrict__ bout, float* __restrict__ out) {
    __shared__ float sW[HID * N_ACT];
    int tid = threadIdx.x;
    for (int t = tid; t < HID * N_ACT; t += 256) sW[t] = Wout[t];
    __syncthreads();

    int row = blockIdx.x * 16 + (tid >> 4);
    int col = tid & 15;
    if (row >= N_DST) return;
    const float* hr = h + (size_t)row * HID;
    float acc = bout[col];
    #pragma unroll 8
    for (int k = 0; k < HID; k++) acc = fmaf(hr[k], sW[k * N_ACT + col], acc);
    out[(size_t)row * N_ACT + col] = acc;
}

// ---------------- launch ----------------
extern "C" void kernel_launch(void* const* d_in, const int* in_sizes, int n_in,
                              void* d_out, int out_size) {
    const float* feat_gt    = (const float*)d_in[0];
    const float* feat_agent = (const float*)d_in[1];
    const float* h0         = (const float*)d_in[2];
    const int*   edge_src   = (const int*)d_in[3];
    const int*   edge_dst   = (const int*)d_in[4];
    const float* W_src      = (const float*)d_in[5];
    const float* b_src      = (const float*)d_in[6];
    const float* W_dst      = (const float*)d_in[7];
    const float* b_dst      = (const float*)d_in[8];
    const float* attn       = (const float*)d_in[9];
    const float* W_res      = (const float*)d_in[10];
    const float* b_res      = (const float*)d_in[11];
    const float* W_ih       = (const float*)d_in[12];
    const float* W_hh       = (const float*)d_in[13];
    const float* b_ih       = (const float*)d_in[14];
    const float* b_hh       = (const float*)d_in[15];
    const float* W_out      = (const float*)d_in[16];
    const float* b_out      = (const float*)d_in[17];

    float* out_logits = (float*)d_out;
    float* out_h      = (float*)d_out + (size_t)N_DST * N_ACT;

    float *p_fs, *p_fd, *p_res, *p_x, *p_gi, *p_gh;
    cudaGetSymbolAddress((void**)&p_fs,  g_fs);
    cudaGetSymbolAddress((void**)&p_fd,  g_fd);
    cudaGetSymbolAddress((void**)&p_res, g_res);
    cudaGetSymbolAddress((void**)&p_x,   g_x);
    cudaGetSymbolAddress((void**)&p_gi,  g_gi);
    cudaGetSymbolAddress((void**)&p_gh,  g_gh);

    const int NELEM = N_DST * HID;
    const int MB = (N_DST + 127) / 128;   // 391 row-blocks

    init_kernel<<<(NELEM + 255) / 256, 256>>>();

    // feature projections (K=64, N=256)
    mmagemm<false><<<dim3(HID / 128, MB), 256>>>(feat_gt,    W_src, b_src, p_fs,  N_SRC, HID, D_IN);
    mmagemm<false><<<dim3(HID / 128, MB), 256>>>(feat_agent, W_dst, b_dst, p_fd,  N_DST, HID, D_IN);
    mmagemm<false><<<dim3(HID / 128, MB), 256>>>(feat_agent, W_res, b_res, p_res, N_DST, HID, D_IN);

    // GATv2 edge passes
    edge_score_kernel<<<(E_NUM + 7) / 8, 256>>>(edge_src, edge_dst, attn);
    edge_msg_kernel<<<(E_NUM + 7) / 8, 256>>>(edge_src, edge_dst);
    node_post_kernel<<<(NELEM + 255) / 256, 256>>>();

    // GRU gates (A @ W^T, K=256, N=768)
    mmagemm<true><<<dim3(G3 / 128, MB), 256>>>(p_x, W_ih, b_ih, p_gi, N_DST, G3, HID);
    mmagemm<true><<<dim3(G3 / 128, MB), 256>>>(h0,  W_hh, b_hh, p_gh, N_DST, G3, HID);

    gru_kernel<<<(NELEM + 255) / 256, 256>>>(h0, out_h);

    logits_kernel<<<(N_DST + 15) / 16, 256>>>(out_h, W_out, b_out, out_logits);
}

// round 5
// speedup vs baseline: 1.9357x; 1.1706x over previous
#include <cuda_runtime.h>
#include <math.h>
#include <stdint.h>

#define N_SRC 50000
#define N_DST 50000
#define E_NUM 800000
#define D_IN  64
#define HID   256
#define HEADS 4
#define FPH   64
#define N_ACT 16
#define G3    (3*HID)   // 768

// ---------------- scratch (device globals; no runtime allocation) ----------------
__device__ float g_fs[(size_t)N_SRC * HID];
__device__ float g_fd[(size_t)N_DST * HID];
__device__ float g_res[(size_t)N_DST * HID];
__device__ float g_x[(size_t)N_DST * HID];
__device__ float g_score[(size_t)E_NUM * HEADS];
__device__ float g_smax[(size_t)N_DST * HEADS];
__device__ float g_den[(size_t)N_DST * HEADS];
__device__ float g_gi[(size_t)N_DST * G3];
__device__ float g_gh[(size_t)N_DST * G3];

// ---------------- helpers ----------------
__device__ __forceinline__ void atomicMaxFloat(float* addr, float val) {
    if (val >= 0.0f) atomicMax((int*)addr, __float_as_int(val));
    else             atomicMin((unsigned int*)addr, __float_as_uint(val));
}

__device__ __forceinline__ void redAddV4(float* p, float a, float b, float c, float d) {
    asm volatile("red.global.add.v4.f32 [%0], {%1,%2,%3,%4};"
                 :: "l"(p), "f"(a), "f"(b), "f"(c), "f"(d) : "memory");
}

// split v into tf32 hi + fp32 remainder (MMA truncates lo to tf32 itself)
__device__ __forceinline__ void tf32split(float v, uint32_t& hi, uint32_t& lo) {
    float h;
    asm("cvt.rna.tf32.f32 %0, %1;" : "=f"(h) : "f"(v));
    hi = __float_as_uint(h);
    lo = __float_as_uint(v - h);
}

#define MMA_TF32(c, a, b)                                                      \
    asm volatile("mma.sync.aligned.m16n8k8.row.col.f32.tf32.tf32.f32 "        \
                 "{%0,%1,%2,%3}, {%4,%5,%6,%7}, {%8,%9}, {%0,%1,%2,%3};"      \
                 : "+f"((c)[0]), "+f"((c)[1]), "+f"((c)[2]), "+f"((c)[3])      \
                 : "r"((a)[0]), "r"((a)[1]), "r"((a)[2]), "r"((a)[3]),        \
                   "r"((b)[0]), "r"((b)[1]))

// ---------------- init ----------------
__global__ void init_kernel() {
    int idx = blockIdx.x * blockDim.x + threadIdx.x;
    if (idx < N_DST * HID) g_x[idx] = 0.0f;
    if (idx < N_DST * HEADS) {
        g_smax[idx] = -INFINITY;
        g_den[idx]  = 0.0f;
    }
}

// ---------------- split-TF32 tensor-core GEMM v2 ----------------
// C[M,N] = A[M,K] @ op(B) + bias, fp32-accurate via 3-term tf32 split.
// 128x128x16 block tile, 512 threads (16 warps, 4x4 grid, 32x32 warp tile),
// raw-fp32 smem (split in registers), double buffered, conflict-free layouts.
// Requires N % 128 == 0, K % 16 == 0. M guarded.
#define SKA 20    // [row][k] stride for A and BT-B (gcd trick: 20*gr spans banks)
#define SKB 136   // [k][n] stride for !BT B

template <bool BT>
__global__ __launch_bounds__(512, 1)
void mmagemm(const float* __restrict__ A, const float* __restrict__ B,
             const float* __restrict__ bias, float* __restrict__ C,
             int M, int N, int K) {
    __shared__ float As[2][128 * SKA];
    __shared__ float Bs[2][128 * SKA];   // !BT uses 16*SKB=2176 <= 2560

    const int tid  = threadIdx.x;
    const int lane = tid & 31;
    const int warp = tid >> 5;
    const int wm   = warp >> 2;          // 0..3
    const int wn   = warp & 3;           // 0..3
    const int m0   = blockIdx.y * 128;
    const int n0   = blockIdx.x * 128;

    const int lrow = tid >> 2;           // 0..127
    const int lk4  = (tid & 3) * 4;      // 0,4,8,12
    const int bk   = tid >> 5;           // 0..15   (!BT B loader)
    const int bn4  = (tid & 31) * 4;     // 0..124

    const int nk = K / 16;
    float4 ra, rb;

    auto fetch = [&](int k0) {
        int r = m0 + lrow;
        ra = (r < M) ? *(const float4*)(A + (size_t)r * K + k0 + lk4)
                     : make_float4(0.f, 0.f, 0.f, 0.f);
        if (BT) rb = *(const float4*)(B + (size_t)(n0 + lrow) * K + k0 + lk4);
        else    rb = *(const float4*)(B + (size_t)(k0 + bk) * N + n0 + bn4);
    };
    auto storeTile = [&](int b) {
        *(float4*)&As[b][lrow * SKA + lk4] = ra;
        if (BT) *(float4*)&Bs[b][lrow * SKA + lk4] = rb;
        else    *(float4*)&Bs[b][bk * SKB + bn4]   = rb;
    };

    float c[2][4][4] = {};

    fetch(0); storeTile(0);
    __syncthreads();

    const int gr = lane >> 2;   // 0..7
    const int gc = lane & 3;    // 0..3

    for (int t = 0; t < nk; t++) {
        if (t + 1 < nk) fetch((t + 1) * 16);

        const float* Ab = As[t & 1];
        const float* Bb = Bs[t & 1];

        #pragma unroll
        for (int k8 = 0; k8 < 16; k8 += 8) {
            uint32_t ah[2][4], al[2][4], bh[4][2], bl[4][2];
            #pragma unroll
            for (int mt = 0; mt < 2; mt++) {
                int mb = wm * 32 + mt * 16 + gr;
                tf32split(Ab[mb * SKA + k8 + gc],           ah[mt][0], al[mt][0]);
                tf32split(Ab[(mb + 8) * SKA + k8 + gc],     ah[mt][1], al[mt][1]);
                tf32split(Ab[mb * SKA + k8 + 4 + gc],       ah[mt][2], al[mt][2]);
                tf32split(Ab[(mb + 8) * SKA + k8 + 4 + gc], ah[mt][3], al[mt][3]);
            }
            #pragma unroll
            for (int nt = 0; nt < 4; nt++) {
                int nb = wn * 32 + nt * 8 + gr;
                float b0 = BT ? Bb[nb * SKA + k8 + gc]     : Bb[(k8 + gc) * SKB + nb];
                float b1 = BT ? Bb[nb * SKA + k8 + 4 + gc] : Bb[(k8 + 4 + gc) * SKB + nb];
                tf32split(b0, bh[nt][0], bl[nt][0]);
                tf32split(b1, bh[nt][1], bl[nt][1]);
            }
            #pragma unroll
            for (int mt = 0; mt < 2; mt++)
                #pragma unroll
                for (int nt = 0; nt < 4; nt++) {
                    MMA_TF32(c[mt][nt], ah[mt], bh[nt]);
                    MMA_TF32(c[mt][nt], ah[mt], bl[nt]);
                    MMA_TF32(c[mt][nt], al[mt], bh[nt]);
                }
        }

        if (t + 1 < nk) {
            storeTile((t + 1) & 1);
            __syncthreads();
        }
    }

    // epilogue: bias + store
    #pragma unroll
    for (int mt = 0; mt < 2; mt++) {
        #pragma unroll
        for (int nt = 0; nt < 4; nt++) {
            int row = m0 + wm * 32 + mt * 16 + gr;
            int col = n0 + wn * 32 + nt * 8 + gc * 2;
            float b0 = bias[col], b1 = bias[col + 1];
            if (row < M) {
                float2 v = make_float2(c[mt][nt][0] + b0, c[mt][nt][1] + b1);
                *(float2*)(C + (size_t)row * N + col) = v;
            }
            if (row + 8 < M) {
                float2 v = make_float2(c[mt][nt][2] + b0, c[mt][nt][3] + b1);
                *(float2*)(C + (size_t)(row + 8) * N + col) = v;
            }
        }
    }
}

// ---------------- edge pass 1: scores + segment max ----------------
__global__ void edge_score_kernel(const int* __restrict__ esrc, const int* __restrict__ edst,
                                  const float* __restrict__ attn) {
    __shared__ float s_attn[HID];
    int tid = threadIdx.x;
    s_attn[tid] = attn[tid];
    __syncthreads();

    int warp = tid >> 5, lane = tid & 31;
    int e = blockIdx.x * 8 + warp;
    if (e >= E_NUM) return;
    int s = esrc[e], d = edst[e];

    const float4* pfs = (const float4*)(g_fs + (size_t)s * HID + lane * 8);
    const float4* pfd = (const float4*)(g_fd + (size_t)d * HID + lane * 8);
    float4 a0 = pfs[0], a1 = pfs[1];
    float4 b0 = pfd[0], b1 = pfd[1];
    const float* at = s_attn + lane * 8;

    float sum = 0.0f, v;
    v = a0.x + b0.x; v = fmaxf(v, 0.2f * v); sum = fmaf(v, at[0], sum);
    v = a0.y + b0.y; v = fmaxf(v, 0.2f * v); sum = fmaf(v, at[1], sum);
    v = a0.z + b0.z; v = fmaxf(v, 0.2f * v); sum = fmaf(v, at[2], sum);
    v = a0.w + b0.w; v = fmaxf(v, 0.2f * v); sum = fmaf(v, at[3], sum);
    v = a1.x + b1.x; v = fmaxf(v, 0.2f * v); sum = fmaf(v, at[4], sum);
    v = a1.y + b1.y; v = fmaxf(v, 0.2f * v); sum = fmaf(v, at[5], sum);
    v = a1.z + b1.z; v = fmaxf(v, 0.2f * v); sum = fmaf(v, at[6], sum);
    v = a1.w + b1.w; v = fmaxf(v, 0.2f * v); sum = fmaf(v, at[7], sum);

    sum += __shfl_down_sync(0xffffffffu, sum, 4, 8);
    sum += __shfl_down_sync(0xffffffffu, sum, 2, 8);
    sum += __shfl_down_sync(0xffffffffu, sum, 1, 8);

    if ((lane & 7) == 0) {
        int h = lane >> 3;
        g_score[(size_t)e * HEADS + h] = sum;
        atomicMaxFloat(&g_smax[(size_t)d * HEADS + h], sum);
    }
}

// ---------------- edge pass 2: exp + denom + message scatter (vector RED) ----------------
__global__ void edge_msg_kernel(const int* __restrict__ esrc, const int* __restrict__ edst) {
    int tid = threadIdx.x;
    int warp = tid >> 5, lane = tid & 31;
    int e = blockIdx.x * 8 + warp;
    if (e >= E_NUM) return;
    int s = esrc[e], d = edst[e];

    int h = lane >> 3;
    float sc = g_score[(size_t)e * HEADS + h];
    float mx = g_smax[(size_t)d * HEADS + h];
    float ex = __expf(sc - mx);
    if ((lane & 7) == 0) atomicAdd(&g_den[(size_t)d * HEADS + h], ex);

    const float4* pfs = (const float4*)(g_fs + (size_t)s * HID + lane * 8);
    float4 a0 = pfs[0], a1 = pfs[1];
    float* px = g_x + (size_t)d * HID + lane * 8;
    redAddV4(px,     ex * a0.x, ex * a0.y, ex * a0.z, ex * a0.w);
    redAddV4(px + 4, ex * a1.x, ex * a1.y, ex * a1.z, ex * a1.w);
}

// ---------------- node epilogue: normalize, residual, relu ----------------
__global__ void node_post_kernel() {
    int idx = blockIdx.x * blockDim.x + threadIdx.x;
    if (idx >= N_DST * HID) return;
    int i = idx >> 8;
    int j = idx & 255;
    int h = j >> 6;
    float dnm = g_den[(size_t)i * HEADS + h];
    float v = (dnm > 0.0f) ? (g_x[idx] / dnm) : 0.0f;
    v += g_res[idx];
    g_x[idx] = fmaxf(v, 0.0f);
}

// ---------------- GRU elementwise (vectorized) ----------------
__global__ void gru_kernel(const float* __restrict__ h0, float* __restrict__ hout) {
    int idx = blockIdx.x * blockDim.x + threadIdx.x;   // one float4 per thread
    if (idx >= N_DST * HID / 4) return;
    int i = idx >> 6;            // node
    int j = (idx & 63) * 4;      // feature base
    size_t b = (size_t)i * G3;

    float4 gir = *(const float4*)(g_gi + b + j);
    float4 ghr = *(const float4*)(g_gh + b + j);
    float4 giz = *(const float4*)(g_gi + b + HID + j);
    float4 ghz = *(const float4*)(g_gh + b + HID + j);
    float4 gin = *(const float4*)(g_gi + b + 2 * HID + j);
    float4 ghn = *(const float4*)(g_gh + b + 2 * HID + j);
    float4 h = *(const float4*)(h0 + (size_t)i * HID + j);

    float4 o;
    {
        float r = 1.0f / (1.0f + expf(-(gir.x + ghr.x)));
        float z = 1.0f / (1.0f + expf(-(giz.x + ghz.x)));
        float n = tanhf(gin.x + r * ghn.x);
        o.x = (1.0f - z) * n + z * h.x;
    }
    {
        float r = 1.0f / (1.0f + expf(-(gir.y + ghr.y)));
        float z = 1.0f / (1.0f + expf(-(giz.y + ghz.y)));
        float n = tanhf(gin.y + r * ghn.y);
        o.y = (1.0f - z) * n + z * h.y;
    }
    {
        float r = 1.0f / (1.0f + expf(-(gir.z + ghr.z)));
        float z = 1.0f / (1.0f + expf(-(giz.z + ghz.z)));
        float n = tanhf(gin.z + r * ghn.z);
        o.z = (1.0f - z) * n + z * h.z;
    }
    {
        float r = 1.0f / (1.0f + expf(-(gir.w + ghr.w)));
        float z = 1.0f / (1.0f + expf(-(giz.w + ghz.w)));
        float n = tanhf(gin.w + r * ghn.w);
        o.w = (1.0f - z) * n + z * h.w;
    }
    *(float4*)(hout + (size_t)i * HID + j) = o;
}

// ---------------- logits head ----------------
__global__ void logits_kernel(const float* __restrict__ h, const float* __restrict__ Wout,
                              const float* __restrict__ bout, float* __restrict__ out) {
    __shared__ float sW[HID * N_ACT];
    int tid = threadIdx.x;
    for (int t = tid; t < HID * N_ACT; t += 256) sW[t] = Wout[t];
    __syncthreads();

    int row = blockIdx.x * 16 + (tid >> 4);
    int col = tid & 15;
    if (row >= N_DST) return;
    const float* hr = h + (size_t)row * HID;
    float acc = bout[col];
    #pragma unroll 8
    for (int k = 0; k < HID; k++) acc = fmaf(hr[k], sW[k * N_ACT + col], acc);
    out[(size_t)row * N_ACT + col] = acc;
}

// ---------------- launch ----------------
extern "C" void kernel_launch(void* const* d_in, const int* in_sizes, int n_in,
                              void* d_out, int out_size) {
    const float* feat_gt    = (const float*)d_in[0];
    const float* feat_agent = (const float*)d_in[1];
    const float* h0         = (const float*)d_in[2];
    const int*   edge_src   = (const int*)d_in[3];
    const int*   edge_dst   = (const int*)d_in[4];
    const float* W_src      = (const float*)d_in[5];
    const float* b_src      = (const float*)d_in[6];
    const float* W_dst      = (const float*)d_in[7];
    const float* b_dst      = (const float*)d_in[8];
    const float* attn       = (const float*)d_in[9];
    const float* W_res      = (const float*)d_in[10];
    const float* b_res      = (const float*)d_in[11];
    const float* W_ih       = (const float*)d_in[12];
    const float* W_hh       = (const float*)d_in[13];
    const float* b_ih       = (const float*)d_in[14];
    const float* b_hh       = (const float*)d_in[15];
    const float* W_out      = (const float*)d_in[16];
    const float* b_out      = (const float*)d_in[17];

    float* out_logits = (float*)d_out;
    float* out_h      = (float*)d_out + (size_t)N_DST * N_ACT;

    float *p_fs, *p_fd, *p_res, *p_x, *p_gi, *p_gh;
    cudaGetSymbolAddress((void**)&p_fs,  g_fs);
    cudaGetSymbolAddress((void**)&p_fd,  g_fd);
    cudaGetSymbolAddress((void**)&p_res, g_res);
    cudaGetSymbolAddress((void**)&p_x,   g_x);
    cudaGetSymbolAddress((void**)&p_gi,  g_gi);
    cudaGetSymbolAddress((void**)&p_gh,  g_gh);

    const int NELEM = N_DST * HID;
    const int MB = (N_DST + 127) / 128;   // 391 row-blocks

    init_kernel<<<(NELEM + 255) / 256, 256>>>();

    // feature projections (K=64, N=256)
    mmagemm<false><<<dim3(HID / 128, MB), 512>>>(feat_gt,    W_src, b_src, p_fs,  N_SRC, HID, D_IN);
    mmagemm<false><<<dim3(HID / 128, MB), 512>>>(feat_agent, W_dst, b_dst, p_fd,  N_DST, HID, D_IN);
    mmagemm<false><<<dim3(HID / 128, MB), 512>>>(feat_agent, W_res, b_res, p_res, N_DST, HID, D_IN);

    // GATv2 edge passes
    edge_score_kernel<<<(E_NUM + 7) / 8, 256>>>(edge_src, edge_dst, attn);
    edge_msg_kernel<<<(E_NUM + 7) / 8, 256>>>(edge_src, edge_dst);
    node_post_kernel<<<(NELEM + 255) / 256, 256>>>();

    // GRU gates (A @ W^T, K=256, N=768)
    mmagemm<true><<<dim3(G3 / 128, MB), 512>>>(p_x, W_ih, b_ih, p_gi, N_DST, G3, HID);
    mmagemm<true><<<dim3(G3 / 128, MB), 512>>>(h0,  W_hh, b_hh, p_gh, N_DST, G3, HID);

    gru_kernel<<<(NELEM / 4 + 255) / 256, 256>>>(h0, out_h);

    logits_kernel<<<(N_DST + 15) / 16, 256>>>(out_h, W_out, b_out, out_logits);
}

// round 6
// speedup vs baseline: 2.3106x; 1.1937x over previous
#include <cuda_runtime.h>
#include <math.h>
#include <stdint.h>

#define N_SRC 50000
#define N_DST 50000
#define E_NUM 800000
#define D_IN  64
#define HID   256
#define HEADS 4
#define FPH   64
#define N_ACT 16
#define G3    (3*HID)   // 768

// ---------------- scratch (device globals; no runtime allocation) ----------------
__device__ float g_fs[(size_t)N_SRC * HID];
__device__ float g_fd[(size_t)N_DST * HID];
__device__ float g_res[(size_t)N_DST * HID];
__device__ float g_x[(size_t)N_DST * HID];
__device__ float g_gi[(size_t)N_DST * G3];
__device__ float g_gh[(size_t)N_DST * G3];
__device__ int   g_deg[N_DST];
__device__ int   g_cursor[N_DST];
__device__ int   g_rowstart[N_DST + 1];
__device__ int   g_csrc[E_NUM];

// ---------------- helpers ----------------
// split v into tf32 hi + fp32 remainder (MMA truncates lo to tf32 itself)
__device__ __forceinline__ void tf32split(float v, uint32_t& hi, uint32_t& lo) {
    float h;
    asm("cvt.rna.tf32.f32 %0, %1;" : "=f"(h) : "f"(v));
    hi = __float_as_uint(h);
    lo = __float_as_uint(v - h);
}

#define MMA_TF32(c, a, b)                                                      \
    asm volatile("mma.sync.aligned.m16n8k8.row.col.f32.tf32.tf32.f32 "        \
                 "{%0,%1,%2,%3}, {%4,%5,%6,%7}, {%8,%9}, {%0,%1,%2,%3};"      \
                 : "+f"((c)[0]), "+f"((c)[1]), "+f"((c)[2]), "+f"((c)[3])      \
                 : "r"((a)[0]), "r"((a)[1]), "r"((a)[2]), "r"((a)[3]),        \
                   "r"((b)[0]), "r"((b)[1]))

// ---------------- split-TF32 tensor-core GEMM ----------------
// C[M,N] = A[M,K] @ op(B) + bias, fp32-accurate via 3-term tf32 split.
// 128x128x16 block tile, 512 threads (16 warps, 4x4 grid, 32x32 warp tile).
#define SKA 20
#define SKB 136

template <bool BT>
__global__ __launch_bounds__(512, 1)
void mmagemm(const float* __restrict__ A, const float* __restrict__ B,
             const float* __restrict__ bias, float* __restrict__ C,
             int M, int N, int K) {
    __shared__ float As[2][128 * SKA];
    __shared__ float Bs[2][128 * SKA];

    const int tid  = threadIdx.x;
    const int lane = tid & 31;
    const int warp = tid >> 5;
    const int wm   = warp >> 2;
    const int wn   = warp & 3;
    const int m0   = blockIdx.y * 128;
    const int n0   = blockIdx.x * 128;

    const int lrow = tid >> 2;
    const int lk4  = (tid & 3) * 4;
    const int bk   = tid >> 5;
    const int bn4  = (tid & 31) * 4;

    const int nk = K / 16;
    float4 ra, rb;

    auto fetch = [&](int k0) {
        int r = m0 + lrow;
        ra = (r < M) ? *(const float4*)(A + (size_t)r * K + k0 + lk4)
                     : make_float4(0.f, 0.f, 0.f, 0.f);
        if (BT) rb = *(const float4*)(B + (size_t)(n0 + lrow) * K + k0 + lk4);
        else    rb = *(const float4*)(B + (size_t)(k0 + bk) * N + n0 + bn4);
    };
    auto storeTile = [&](int b) {
        *(float4*)&As[b][lrow * SKA + lk4] = ra;
        if (BT) *(float4*)&Bs[b][lrow * SKA + lk4] = rb;
        else    *(float4*)&Bs[b][bk * SKB + bn4]   = rb;
    };

    float c[2][4][4] = {};

    fetch(0); storeTile(0);
    __syncthreads();

    const int gr = lane >> 2;
    const int gc = lane & 3;

    for (int t = 0; t < nk; t++) {
        if (t + 1 < nk) fetch((t + 1) * 16);

        const float* Ab = As[t & 1];
        const float* Bb = Bs[t & 1];

        #pragma unroll
        for (int k8 = 0; k8 < 16; k8 += 8) {
            uint32_t ah[2][4], al[2][4], bh[4][2], bl[4][2];
            #pragma unroll
            for (int mt = 0; mt < 2; mt++) {
                int mb = wm * 32 + mt * 16 + gr;
                tf32split(Ab[mb * SKA + k8 + gc],           ah[mt][0], al[mt][0]);
                tf32split(Ab[(mb + 8) * SKA + k8 + gc],     ah[mt][1], al[mt][1]);
                tf32split(Ab[mb * SKA + k8 + 4 + gc],       ah[mt][2], al[mt][2]);
                tf32split(Ab[(mb + 8) * SKA + k8 + 4 + gc], ah[mt][3], al[mt][3]);
            }
            #pragma unroll
            for (int nt = 0; nt < 4; nt++) {
                int nb = wn * 32 + nt * 8 + gr;
                float b0 = BT ? Bb[nb * SKA + k8 + gc]     : Bb[(k8 + gc) * SKB + nb];
                float b1 = BT ? Bb[nb * SKA + k8 + 4 + gc] : Bb[(k8 + 4 + gc) * SKB + nb];
                tf32split(b0, bh[nt][0], bl[nt][0]);
                tf32split(b1, bh[nt][1], bl[nt][1]);
            }
            #pragma unroll
            for (int mt = 0; mt < 2; mt++)
                #pragma unroll
                for (int nt = 0; nt < 4; nt++) {
                    MMA_TF32(c[mt][nt], ah[mt], bh[nt]);
                    MMA_TF32(c[mt][nt], ah[mt], bl[nt]);
                    MMA_TF32(c[mt][nt], al[mt], bh[nt]);
                }
        }

        if (t + 1 < nk) {
            storeTile((t + 1) & 1);
            __syncthreads();
        }
    }

    #pragma unroll
    for (int mt = 0; mt < 2; mt++) {
        #pragma unroll
        for (int nt = 0; nt < 4; nt++) {
            int row = m0 + wm * 32 + mt * 16 + gr;
            int col = n0 + wn * 32 + nt * 8 + gc * 2;
            float b0 = bias[col], b1 = bias[col + 1];
            if (row < M) {
                float2 v = make_float2(c[mt][nt][0] + b0, c[mt][nt][1] + b1);
                *(float2*)(C + (size_t)row * N + col) = v;
            }
            if (row + 8 < M) {
                float2 v = make_float2(c[mt][nt][2] + b0, c[mt][nt][3] + b1);
                *(float2*)(C + (size_t)(row + 8) * N + col) = v;
            }
        }
    }
}

// ---------------- CSR build ----------------
__global__ void hist_kernel(const int* __restrict__ edst) {
    int e = blockIdx.x * blockDim.x + threadIdx.x;
    if (e < E_NUM) atomicAdd(&g_deg[edst[e]], 1);
}

// single-block exclusive scan over g_deg -> g_rowstart
__global__ void scan_kernel() {
    __shared__ int sh[1024];
    __shared__ int carry;
    int tid = threadIdx.x;
    if (tid == 0) carry = 0;
    __syncthreads();
    for (int base = 0; base < N_DST; base += 1024) {
        int v = (base + tid < N_DST) ? g_deg[base + tid] : 0;
        sh[tid] = v;
        __syncthreads();
        #pragma unroll
        for (int off = 1; off < 1024; off <<= 1) {
            int t = (tid >= off) ? sh[tid - off] : 0;
            __syncthreads();
            sh[tid] += t;
            __syncthreads();
        }
        if (base + tid < N_DST) g_rowstart[base + tid] = carry + sh[tid] - v;
        __syncthreads();
        if (tid == 0) carry += sh[1023];
        __syncthreads();
    }
    if (threadIdx.x == 0) g_rowstart[N_DST] = E_NUM;
}

__global__ void fill_kernel(const int* __restrict__ esrc, const int* __restrict__ edst) {
    int e = blockIdx.x * blockDim.x + threadIdx.x;
    if (e >= E_NUM) return;
    int d = edst[e];
    int pos = atomicAdd(&g_cursor[d], 1);
    g_csrc[g_rowstart[d] + pos] = esrc[e];
}

// ---------------- fused GAT node kernel ----------------
// block = 1 dst node, warp = 1 head, lane = 2 features.
// Online softmax over the node's edge list: single pass over fs gathers,
// register accumulation, fused normalize + residual + ReLU.
__global__ __launch_bounds__(128)
void gat_node_kernel(const float* __restrict__ attn) {
    const int i    = blockIdx.x;
    const int warp = threadIdx.x >> 5;    // head
    const int lane = threadIdx.x & 31;
    const int fo   = warp * FPH + lane * 2;

    const int beg = g_rowstart[i];
    const int end = g_rowstart[i + 1];

    const float2 fd = *(const float2*)(g_fd + (size_t)i * HID + fo);
    const float2 at = *(const float2*)(attn + fo);

    float m = -INFINITY, den = 0.0f, ax = 0.0f, ay = 0.0f;

    if (beg < end) {
        int s = g_csrc[beg];
        float2 f = *(const float2*)(g_fs + (size_t)s * HID + fo);
        for (int j = beg; j < end; j++) {
            // prefetch next edge's features to hide gather latency behind the reduce
            float2 fn;
            if (j + 1 < end) {
                int sn = g_csrc[j + 1];
                fn = *(const float2*)(g_fs + (size_t)sn * HID + fo);
            }
            float v0 = f.x + fd.x; v0 = fmaxf(v0, 0.2f * v0);
            float v1 = f.y + fd.y; v1 = fmaxf(v1, 0.2f * v1);
            float sc = fmaf(v0, at.x, v1 * at.y);
            #pragma unroll
            for (int o = 16; o; o >>= 1) sc += __shfl_xor_sync(0xffffffffu, sc, o);

            float mn  = fmaxf(m, sc);
            float scl = __expf(m - mn);
            float ex  = __expf(sc - mn);
            den = fmaf(den, scl, ex);
            ax  = fmaf(ax, scl, ex * f.x);
            ay  = fmaf(ay, scl, ex * f.y);
            m = mn;
            f = fn;
        }
    }

    float inv = (den > 0.0f) ? (1.0f / den) : 0.0f;
    float2 rs = *(const float2*)(g_res + (size_t)i * HID + fo);
    float2 o;
    o.x = fmaxf(fmaf(ax, inv, rs.x), 0.0f);
    o.y = fmaxf(fmaf(ay, inv, rs.y), 0.0f);
    *(float2*)(g_x + (size_t)i * HID + fo) = o;
}

// ---------------- GRU elementwise (vectorized) ----------------
__global__ void gru_kernel(const float* __restrict__ h0, float* __restrict__ hout) {
    int idx = blockIdx.x * blockDim.x + threadIdx.x;
    if (idx >= N_DST * HID / 4) return;
    int i = idx >> 6;
    int j = (idx & 63) * 4;
    size_t b = (size_t)i * G3;

    float4 gir = *(const float4*)(g_gi + b + j);
    float4 ghr = *(const float4*)(g_gh + b + j);
    float4 giz = *(const float4*)(g_gi + b + HID + j);
    float4 ghz = *(const float4*)(g_gh + b + HID + j);
    float4 gin = *(const float4*)(g_gi + b + 2 * HID + j);
    float4 ghn = *(const float4*)(g_gh + b + 2 * HID + j);
    float4 h = *(const float4*)(h0 + (size_t)i * HID + j);

    float4 o;
    {
        float r = 1.0f / (1.0f + expf(-(gir.x + ghr.x)));
        float z = 1.0f / (1.0f + expf(-(giz.x + ghz.x)));
        float n = tanhf(gin.x + r * ghn.x);
        o.x = (1.0f - z) * n + z * h.x;
    }
    {
        float r = 1.0f / (1.0f + expf(-(gir.y + ghr.y)));
        float z = 1.0f / (1.0f + expf(-(giz.y + ghz.y)));
        float n = tanhf(gin.y + r * ghn.y);
        o.y = (1.0f - z) * n + z * h.y;
    }
    {
        float r = 1.0f / (1.0f + expf(-(gir.z + ghr.z)));
        float z = 1.0f / (1.0f + expf(-(giz.z + ghz.z)));
        float n = tanhf(gin.z + r * ghn.z);
        o.z = (1.0f - z) * n + z * h.z;
    }
    {
        float r = 1.0f / (1.0f + expf(-(gir.w + ghr.w)));
        float z = 1.0f / (1.0f + expf(-(giz.w + ghz.w)));
        float n = tanhf(gin.w + r * ghn.w);
        o.w = (1.0f - z) * n + z * h.w;
    }
    *(float4*)(hout + (size_t)i * HID + j) = o;
}

// ---------------- logits head ----------------
__global__ void logits_kernel(const float* __restrict__ h, const float* __restrict__ Wout,
                              const float* __restrict__ bout, float* __restrict__ out) {
    __shared__ float sW[HID * N_ACT];
    int tid = threadIdx.x;
    for (int t = tid; t < HID * N_ACT; t += 256) sW[t] = Wout[t];
    __syncthreads();

    int row = blockIdx.x * 16 + (tid >> 4);
    int col = tid & 15;
    if (row >= N_DST) return;
    const float* hr = h + (size_t)row * HID;
    float acc = bout[col];
    #pragma unroll 8
    for (int k = 0; k < HID; k++) acc = fmaf(hr[k], sW[k * N_ACT + col], acc);
    out[(size_t)row * N_ACT + col] = acc;
}

// ---------------- launch ----------------
extern "C" void kernel_launch(void* const* d_in, const int* in_sizes, int n_in,
                              void* d_out, int out_size) {
    const float* feat_gt    = (const float*)d_in[0];
    const float* feat_agent = (const float*)d_in[1];
    const float* h0         = (const float*)d_in[2];
    const int*   edge_src   = (const int*)d_in[3];
    const int*   edge_dst   = (const int*)d_in[4];
    const float* W_src      = (const float*)d_in[5];
    const float* b_src      = (const float*)d_in[6];
    const float* W_dst      = (const float*)d_in[7];
    const float* b_dst      = (const float*)d_in[8];
    const float* attn       = (const float*)d_in[9];
    const float* W_res      = (const float*)d_in[10];
    const float* b_res      = (const float*)d_in[11];
    const float* W_ih       = (const float*)d_in[12];
    const float* W_hh       = (const float*)d_in[13];
    const float* b_ih       = (const float*)d_in[14];
    const float* b_hh       = (const float*)d_in[15];
    const float* W_out      = (const float*)d_in[16];
    const float* b_out      = (const float*)d_in[17];

    float* out_logits = (float*)d_out;
    float* out_h      = (float*)d_out + (size_t)N_DST * N_ACT;

    float *p_fs, *p_fd, *p_res, *p_x, *p_gi, *p_gh;
    int *p_deg, *p_cur;
    cudaGetSymbolAddress((void**)&p_fs,  g_fs);
    cudaGetSymbolAddress((void**)&p_fd,  g_fd);
    cudaGetSymbolAddress((void**)&p_res, g_res);
    cudaGetSymbolAddress((void**)&p_x,   g_x);
    cudaGetSymbolAddress((void**)&p_gi,  g_gi);
    cudaGetSymbolAddress((void**)&p_gh,  g_gh);
    cudaGetSymbolAddress((void**)&p_deg, g_deg);
    cudaGetSymbolAddress((void**)&p_cur, g_cursor);

    const int NELEM = N_DST * HID;
    const int MB = (N_DST + 127) / 128;

    // CSR build (overlaps conceptually with projections; same stream ordering is fine)
    cudaMemsetAsync(p_deg, 0, N_DST * sizeof(int));
    cudaMemsetAsync(p_cur, 0, N_DST * sizeof(int));
    hist_kernel<<<(E_NUM + 255) / 256, 256>>>(edge_dst);
    scan_kernel<<<1, 1024>>>();
    fill_kernel<<<(E_NUM + 255) / 256, 256>>>(edge_src, edge_dst);

    // feature projections (K=64, N=256)
    mmagemm<false><<<dim3(HID / 128, MB), 512>>>(feat_gt,    W_src, b_src, p_fs,  N_SRC, HID, D_IN);
    mmagemm<false><<<dim3(HID / 128, MB), 512>>>(feat_agent, W_dst, b_dst, p_fd,  N_DST, HID, D_IN);
    mmagemm<false><<<dim3(HID / 128, MB), 512>>>(feat_agent, W_res, b_res, p_res, N_DST, HID, D_IN);

    // fused GAT: online softmax + aggregation + residual + ReLU
    gat_node_kernel<<<N_DST, 128>>>(attn);

    // GRU gates (A @ W^T, K=256, N=768)
    mmagemm<true><<<dim3(G3 / 128, MB), 512>>>(p_x, W_ih, b_ih, p_gi, N_DST, G3, HID);
    mmagemm<true><<<dim3(G3 / 128, MB), 512>>>(h0,  W_hh, b_hh, p_gh, N_DST, G3, HID);

    gru_kernel<<<(NELEM / 4 + 255) / 256, 256>>>(h0, out_h);

    logits_kernel<<<(N_DST + 15) / 16, 256>>>(out_h, W_out, b_out, out_logits);
}